// round 17
// baseline (speedup 1.0000x reference)
#include <cuda_runtime.h>
#include <cuda_bf16.h>
#include <cuda_fp16.h>
#include <math.h>
#include <stdint.h>

#define BI 4
#define TT 1024
#define CC 1024
#define HH 16
#define DD 64
#define LL 8
#define VV 32000

// fp32 scratch
__device__ float g_x  [BI * TT * CC];
__device__ float g_qkv[BI * TT * 3 * CC];
// fp16 scratch
__device__ __half g_w16[(size_t)LL * 8 * CC * CC];
__device__ __half g_tok16[(size_t)VV * CC];
__device__ __half g_a16[(size_t)BI * TT * CC];
__device__ __half g_m16[(size_t)BI * TT * 2 * CC];
__device__ __half g_q16[(size_t)BI * TT * 3 * CC];
__device__ __half g_v16[(size_t)BI * HH * DD * TT];

// ---------------- helpers ----------------
__device__ __forceinline__ uint32_t smem_u32(const void* p) {
    uint32_t a;
    asm("{ .reg .u64 t; cvta.to.shared.u64 t, %1; cvt.u32.u64 %0, t; }" : "=r"(a) : "l"(p));
    return a;
}
__device__ __forceinline__ void cpa(uint32_t dst, const void* src) {
    asm volatile("cp.async.cg.shared.global [%0], [%1], 16;" :: "r"(dst), "l"(src));
}
__device__ __forceinline__ void ldm4(uint32_t* r, uint32_t addr) {
    asm volatile("ldmatrix.sync.aligned.m8n8.x4.shared.b16 {%0,%1,%2,%3}, [%4];"
                 : "=r"(r[0]), "=r"(r[1]), "=r"(r[2]), "=r"(r[3]) : "r"(addr));
}
__device__ __forceinline__ void mma16816h(float* d, const uint32_t* a, const uint32_t* b) {
    asm volatile("mma.sync.aligned.m16n8k16.row.col.f32.f16.f16.f32 "
                 "{%0,%1,%2,%3}, {%4,%5,%6,%7}, {%8,%9}, {%0,%1,%2,%3};"
                 : "+f"(d[0]), "+f"(d[1]), "+f"(d[2]), "+f"(d[3])
                 : "r"(a[0]), "r"(a[1]), "r"(a[2]), "r"(a[3]), "r"(b[0]), "r"(b[1]));
}
__device__ __forceinline__ float warpSum(float v) {
    #pragma unroll
    for (int o = 16; o > 0; o >>= 1) v += __shfl_xor_sync(0xffffffffu, v, o);
    return v;
}
__device__ __forceinline__ uint32_t pk2h(float x, float y) {
    __half2 h = __floats2half2_rn(x, y);
    return *(uint32_t*)&h;
}
// 64B-row swizzle: chunk c in [0,4), row r -> byte offset
__device__ __forceinline__ uint32_t swz(int r, int c) {
    return (uint32_t)(r * 64 + ((c ^ ((r >> 1) & 3)) << 4));
}

// ---------------- small kernels ----------------
__global__ void embed_kernel(const int* __restrict__ idx, const float* __restrict__ tok,
                             const float* __restrict__ qe, const float* __restrict__ ae,
                             const float* __restrict__ pos) {
    int bt = blockIdx.x, t = bt & (TT - 1), b = bt >> 10;
    int any = 0;
    for (int i = threadIdx.x; i <= t; i += 256) any |= (idx[b * TT + i] == 2);
    any = __syncthreads_or(any);
    const float* emb = tok + (size_t)idx[bt] * CC;
    const float* add = any ? ae : qe;
    for (int i = threadIdx.x; i < CC; i += 256)
        g_x[(size_t)bt * CC + i] = emb[i] + pos[(size_t)t * CC + i] + add[i];
}
// LayerNorm emitting fp16
__global__ void ln16_kernel(const float* __restrict__ in, __half* __restrict__ o16,
                            const float* __restrict__ sc, const float* __restrict__ bi) {
    int row = blockIdx.x;
    const float* xr = in + (size_t)row * CC;
    int tid = threadIdx.x, lane = tid & 31, wid = tid >> 5;
    __shared__ float red[8], s_mean, s_rstd;
    float v[4]; float sum = 0.f;
    #pragma unroll
    for (int i = 0; i < 4; i++) { v[i] = xr[tid + i * 256]; sum += v[i]; }
    sum = warpSum(sum);
    if (lane == 0) red[wid] = sum;
    __syncthreads();
    if (wid == 0) { float t = (lane < 8) ? red[lane] : 0.f; t = warpSum(t); if (lane == 0) s_mean = t * (1.0f / CC); }
    __syncthreads();
    float mean = s_mean, sq = 0.f;
    #pragma unroll
    for (int i = 0; i < 4; i++) { float d = v[i] - mean; sq += d * d; }
    __syncthreads();
    sq = warpSum(sq);
    if (lane == 0) red[wid] = sq;
    __syncthreads();
    if (wid == 0) { float t = (lane < 8) ? red[lane] : 0.f; t = warpSum(t); if (lane == 0) s_rstd = rsqrtf(t * (1.0f / CC) + 1e-5f); }
    __syncthreads();
    float r = s_rstd;
    #pragma unroll
    for (int i = 0; i < 4; i++) {
        int c = tid + i * 256;
        o16[(size_t)row * CC + c] = __float2half((v[i] - mean) * r * sc[c] + bi[c]);
    }
}
// fp32 -> fp16
__global__ void aconv16(const float* __restrict__ a, __half* __restrict__ o, long n) {
    long i = ((long)blockIdx.x * 256 + threadIdx.x) * 4;
    if (i >= n) return;
    float4 v = *(const float4*)(a + i);
    __half h[4] = {__float2half(v.x), __float2half(v.y), __float2half(v.z), __float2half(v.w)};
    *(uint2*)(o + i) = *(uint2*)h;
}
// W [K,N] fp32 -> [N,K] fp16 transpose
__global__ void wconv16(const float* __restrict__ W, __half* __restrict__ o, int K, int N) {
    __shared__ float t[32][33];
    int k0 = blockIdx.y * 32, n0 = blockIdx.x * 32;
    int x = threadIdx.x & 31, y = threadIdx.x >> 5;
    #pragma unroll
    for (int i = 0; i < 32; i += 8) t[y + i][x] = W[(size_t)(k0 + y + i) * N + n0 + x];
    __syncthreads();
    #pragma unroll
    for (int i = 0; i < 32; i += 8)
        o[(size_t)(n0 + y + i) * K + k0 + x] = __float2half(t[x][y + i]);
}
// v third of qkv (fp32) -> Vt [z][d][s] fp16
__global__ void vconv16(const float* __restrict__ qkv) {
    int z = blockIdx.z, b = z >> 4, h = z & 15;
    int s0 = blockIdx.x * 32, d0 = blockIdx.y * 32;
    const float* src = qkv + (size_t)b * TT * 3 * CC + 2 * CC + h * DD;
    __shared__ float t[32][33];
    int x = threadIdx.x & 31, y = threadIdx.x >> 5;
    #pragma unroll
    for (int i = 0; i < 32; i += 8) t[y + i][x] = src[(size_t)(s0 + y + i) * 3 * CC + d0 + x];
    __syncthreads();
    __half* o = g_v16 + (size_t)z * DD * TT;
    #pragma unroll
    for (int i = 0; i < 32; i += 8)
        o[(size_t)(d0 + y + i) * TT + s0 + x] = __float2half(t[x][y + i]);
}

// ---------------- fused flash attention (fp16, 2 CTAs/SM) ----------------
__global__ void __launch_bounds__(256, 2) flash16(
    const __half* __restrict__ q16, const __half* __restrict__ v16,
    __half* __restrict__ y16)
{
    const int bm = (7 - blockIdx.x) * 128;
    const int z = blockIdx.y, b = z >> 4, h = z & 15;
    const long qb = (long)b * TT * 3 * CC + h * DD;
    const __half* Q = q16 + qb;
    const __half* K = q16 + qb + CC;
    const __half* V = v16 + (long)z * DD * TT;

    extern __shared__ char smem[];
    const uint32_t sb = smem_u32(smem);
    const uint32_t oS = 18432, SSZ = 35840;   // stage: K(18432) + V(17408)

    const int tid = threadIdx.x, wid = tid >> 5, lane = tid & 31;
    const int rsel = (lane & 7) + ((lane >> 3) & 1) * 8;
    const int quad = lane >> 4;
    const int r0 = lane >> 2, c0 = (lane & 3) * 2;
    const int row0 = bm + wid * 16 + r0;
    const int nkt = (bm >> 7) + 1;

    const int kr = tid >> 3, kc = tid & 7;
    const int vr = tid >> 4, vc = tid & 15;
    uint32_t koff[4], voff[4];
    const __half *pK[4], *pV[4];
    #pragma unroll
    for (int j = 0; j < 4; j++) {
        int r = kr + j * 32;
        koff[j] = (uint32_t)(r * 144 + kc * 16);
        pK[j] = K + (long)r * 3 * CC + kc * 8;
        int rv = vr + j * 16;
        voff[j] = (uint32_t)(rv * 272 + vc * 16);
        pV[j] = V + (long)rv * TT + vc * 8;
    }

    for (int v = tid; v < 1024; v += 256) {
        int r = v >> 3, c = v & 7;
        cpa(sb + r * 144 + c * 16, Q + (long)(bm + r) * 3 * CC + c * 8);
    }
    {
        uint32_t st = sb + oS;
        #pragma unroll
        for (int j = 0; j < 4; j++) {
            cpa(st + koff[j], pK[j]);          pK[j] += (long)128 * 3 * CC;
            cpa(st + 18432 + voff[j], pV[j]);  pV[j] += 128;
        }
    }
    asm volatile("cp.async.commit_group;" ::: "memory");

    float m0 = -1e30f, m1 = -1e30f, l0 = 0.f, l1 = 0.f;
    float oacc[8][4];
    #pragma unroll
    for (int i = 0; i < 8; i++)
        #pragma unroll
        for (int j = 0; j < 4; j++) oacc[i][j] = 0.f;

    for (int kt = 0; kt < nkt; kt++) {
        int buf = kt & 1;
        if (kt + 1 < nkt) {
            uint32_t sn = sb + oS + (buf ^ 1) * SSZ;
            #pragma unroll
            for (int j = 0; j < 4; j++) {
                cpa(sn + koff[j], pK[j]);          pK[j] += (long)128 * 3 * CC;
                cpa(sn + 18432 + voff[j], pV[j]);  pV[j] += 128;
            }
            asm volatile("cp.async.commit_group;" ::: "memory");
            asm volatile("cp.async.wait_group 1;" ::: "memory");
        } else {
            asm volatile("cp.async.wait_group 0;" ::: "memory");
        }
        __syncthreads();
        uint32_t sk = sb + oS + buf * SSZ;

        // ---- S = Q @ K^T ----
        float sc[16][4];
        #pragma unroll
        for (int i = 0; i < 16; i++)
            #pragma unroll
            for (int j = 0; j < 4; j++) sc[i][j] = 0.f;
        #pragma unroll
        for (int kc2 = 0; kc2 < 4; kc2++) {
            uint32_t aq[4];
            ldm4(aq, sb + (uint32_t)((wid * 16 + rsel) * 144 + kc2 * 32 + quad * 16));
            #pragma unroll
            for (int ngb = 0; ngb < 4; ngb++) {
                uint32_t th[2][4];
                #pragma unroll
                for (int j = 0; j < 2; j++) {
                    int ng = ngb * 2 + j;
                    ldm4(th[j], sk + (uint32_t)((ng * 16 + rsel) * 144 + kc2 * 32 + quad * 16));
                }
                #pragma unroll
                for (int j = 0; j < 2; j++) {
                    int ng = ngb * 2 + j;
                    uint32_t b0[2] = {th[j][0], th[j][2]}, b1[2] = {th[j][1], th[j][3]};
                    mma16816h(sc[2 * ng], aq, b0);
                    mma16816h(sc[2 * ng + 1], aq, b1);
                }
            }
        }
        // ---- causal mask (diagonal tile) ----
        if (kt == nkt - 1) {
            int kb = kt * 128;
            #pragma unroll
            for (int nt = 0; nt < 16; nt++)
                #pragma unroll
                for (int e = 0; e < 2; e++) {
                    int col = kb + nt * 8 + c0 + e;
                    if (col > row0) sc[nt][e] = -1e30f;
                    if (col > row0 + 8) sc[nt][2 + e] = -1e30f;
                }
        }
        // ---- online softmax ----
        float mx0 = -1e30f, mx1 = -1e30f;
        #pragma unroll
        for (int nt = 0; nt < 16; nt++) {
            mx0 = fmaxf(mx0, fmaxf(sc[nt][0], sc[nt][1]));
            mx1 = fmaxf(mx1, fmaxf(sc[nt][2], sc[nt][3]));
        }
        #pragma unroll
        for (int o = 1; o < 4; o <<= 1) {
            mx0 = fmaxf(mx0, __shfl_xor_sync(0xffffffffu, mx0, o));
            mx1 = fmaxf(mx1, __shfl_xor_sync(0xffffffffu, mx1, o));
        }
        float mn0 = fmaxf(m0, mx0), mn1 = fmaxf(m1, mx1);
        float a0 = __expf(m0 - mn0), a1 = __expf(m1 - mn1);
        m0 = mn0; m1 = mn1;
        float s0 = 0.f, s1 = 0.f;
        #pragma unroll
        for (int nt = 0; nt < 16; nt++) {
            sc[nt][0] = __expf(sc[nt][0] - m0); s0 += sc[nt][0];
            sc[nt][1] = __expf(sc[nt][1] - m0); s0 += sc[nt][1];
            sc[nt][2] = __expf(sc[nt][2] - m1); s1 += sc[nt][2];
            sc[nt][3] = __expf(sc[nt][3] - m1); s1 += sc[nt][3];
        }
        #pragma unroll
        for (int o = 1; o < 4; o <<= 1) {
            s0 += __shfl_xor_sync(0xffffffffu, s0, o);
            s1 += __shfl_xor_sync(0xffffffffu, s1, o);
        }
        l0 = l0 * a0 + s0;  l1 = l1 * a1 + s1;
        #pragma unroll
        for (int nt = 0; nt < 8; nt++) {
            oacc[nt][0] *= a0; oacc[nt][1] *= a0;
            oacc[nt][2] *= a1; oacc[nt][3] *= a1;
        }
        // ---- O += P @ V^T ----
        #pragma unroll
        for (int kc2 = 0; kc2 < 8; kc2++) {
            uint32_t p[4];
            p[0] = pk2h(sc[2 * kc2][0],     sc[2 * kc2][1]);
            p[1] = pk2h(sc[2 * kc2][2],     sc[2 * kc2][3]);
            p[2] = pk2h(sc[2 * kc2 + 1][0], sc[2 * kc2 + 1][1]);
            p[3] = pk2h(sc[2 * kc2 + 1][2], sc[2 * kc2 + 1][3]);
            #pragma unroll
            for (int ngb = 0; ngb < 2; ngb++) {
                uint32_t th[2][4];
                #pragma unroll
                for (int j = 0; j < 2; j++) {
                    int ng = ngb * 2 + j;
                    ldm4(th[j], sk + 18432 + (uint32_t)((ng * 16 + rsel) * 272 + kc2 * 32 + quad * 16));
                }
                #pragma unroll
                for (int j = 0; j < 2; j++) {
                    int ng = ngb * 2 + j;
                    uint32_t b0[2] = {th[j][0], th[j][2]}, b1[2] = {th[j][1], th[j][3]};
                    mma16816h(oacc[2 * ng], p, b0);
                    mma16816h(oacc[2 * ng + 1], p, b1);
                }
            }
        }
        __syncthreads();
    }
    float i0 = 1.f / l0, i1 = 1.f / l1;
    #pragma unroll
    for (int nt = 0; nt < 8; nt++)
        #pragma unroll
        for (int e = 0; e < 2; e++) {
            int d = nt * 8 + c0 + e;
            size_t o0 = ((size_t)b * TT + row0) * CC + h * DD + d;
            y16[o0] = __float2half(oacc[nt][e] * i0);
            y16[o0 + 8 * CC] = __float2half(oacc[nt][2 + e] * i1);
        }
}

// ---------------- fp16 GEMM, K-step 64 (2x K32 subtiles/stage) ----------------
// stage 32KB: A0 @0, A1 @8192, B0 @16384, B1 @24576. 64 MMAs per barrier.
// EPI: 0 store fp32; 1 +=; 2 gelu(v+bias)->fp16; 3 +=v+bias;
//      5 qkv: v-cols fp32, q (*0.125) / k cols -> fp16
#define STG16 32768
template <int EPI>
__global__ void __launch_bounds__(256, 2) tg16(
    int M, int N, int K,
    const __half* __restrict__ Ax, long lda,
    const __half* __restrict__ Bx, long ldb,
    const float* __restrict__ bias,
    float* __restrict__ C, long ldc,
    __half* __restrict__ O16)
{
    const int bm = blockIdx.x * 128;
    const int bn = blockIdx.y * 128;

    extern __shared__ char smem[];
    const uint32_t sb0 = smem_u32(smem);
    const int tid = threadIdx.x, wid = tid >> 5, lane = tid & 31;
    const int wm = (wid & 1) * 64, wn = (wid >> 1) * 32;
    const int rsel = (lane & 7) + ((lane >> 3) & 1) * 8;
    const int quad = lane >> 4;

    const int rA = tid >> 2, cth = tid & 3;
    const uint32_t so0 = swz(rA, cth), so1 = swz(64 + rA, cth);
    const __half *pA0 = Ax + (long)(bm + rA) * lda + cth * 8;
    const __half *pA1 = Ax + (long)(bm + 64 + rA) * lda + cth * 8;
    const __half *pB0 = Bx + (long)(bn + rA) * ldb + cth * 8;
    const __half *pB1 = Bx + (long)(bn + 64 + rA) * ldb + cth * 8;

    auto issue_stage = [&](uint32_t st) {
        cpa(st + so0,         pA0);      cpa(st + so1,         pA1);
        cpa(st + 8192 + so0,  pA0 + 32); cpa(st + 8192 + so1,  pA1 + 32);
        cpa(st + 16384 + so0, pB0);      cpa(st + 16384 + so1, pB1);
        cpa(st + 24576 + so0, pB0 + 32); cpa(st + 24576 + so1, pB1 + 32);
        pA0 += 64; pA1 += 64; pB0 += 64; pB1 += 64;
        asm volatile("cp.async.commit_group;" ::: "memory");
    };

    float acc[4][4][4];
    #pragma unroll
    for (int a = 0; a < 4; a++)
        #pragma unroll
        for (int b = 0; b < 4; b++)
            #pragma unroll
            for (int c = 0; c < 4; c++) acc[a][b][c] = 0.f;

    const int nk = K >> 6;
    issue_stage(sb0);
    issue_stage(sb0 + STG16);

    uint32_t stbase[3] = {sb0, sb0 + STG16, sb0 + 2 * STG16};
    int si = 0;
    for (int i = 0; i < nk; i++) {
        if (i + 1 < nk) asm volatile("cp.async.wait_group 1;" ::: "memory");
        else            asm volatile("cp.async.wait_group 0;" ::: "memory");
        __syncthreads();
        if (i + 2 < nk) {
            int sp = si + 2; if (sp >= 3) sp -= 3;
            issue_stage(stbase[sp]);
        }
        uint32_t base = stbase[si];
        #pragma unroll
        for (int sub = 0; sub < 2; sub++) {
            uint32_t abase = base + sub * 8192;
            uint32_t bbase = base + 16384 + sub * 8192;
            #pragma unroll
            for (int ks = 0; ks < 2; ks++) {
                uint32_t ah[4][4], tb[2][4];
                const int cc = ks * 2 + quad;
                #pragma unroll
                for (int mt = 0; mt < 4; mt++)
                    ldm4(ah[mt], abase + swz(wm + mt * 16 + rsel, cc));
                #pragma unroll
                for (int ng = 0; ng < 2; ng++)
                    ldm4(tb[ng], bbase + swz(wn + ng * 16 + rsel, cc));
                #pragma unroll
                for (int mt = 0; mt < 4; mt++)
                    #pragma unroll
                    for (int nt = 0; nt < 4; nt++) {
                        uint32_t bf[2] = {tb[nt >> 1][nt & 1], tb[nt >> 1][2 + (nt & 1)]};
                        mma16816h(acc[mt][nt], ah[mt], bf);
                    }
            }
        }
        if (++si == 3) si = 0;
    }

    const int r0 = lane >> 2, c0 = (lane & 3) * 2;
    #pragma unroll
    for (int mt = 0; mt < 4; mt++)
        #pragma unroll
        for (int nt = 0; nt < 4; nt++)
            #pragma unroll
            for (int hf = 0; hf < 2; hf++) {
                int m = bm + wm + mt * 16 + r0 + hf * 8;
                int n = bn + wn + nt * 8 + c0;
                size_t o = (size_t)m * ldc + n;
                #pragma unroll
                for (int e = 0; e < 2; e++) {
                    float v = acc[mt][nt][hf * 2 + e];
                    size_t oo = o + e;
                    int nn = n + e;
                    if (EPI == 0) C[oo] = v;
                    else if (EPI == 1) C[oo] += v;
                    else if (EPI == 2) {
                        v += bias[nn];
                        v = 0.5f * v * (1.0f + erff(v * 0.70710678f));
                        O16[oo] = __float2half(v);
                    }
                    else if (EPI == 3) C[oo] += v + bias[nn];
                    else if (EPI == 5) {
                        if (nn >= 2 * CC) C[oo] = v;
                        else O16[oo] = __float2half((nn < CC) ? v * 0.125f : v);
                    }
                }
            }
}

// ---------------- host ----------------
extern "C" void kernel_launch(void* const* d_in, const int* in_sizes, int n_in,
                              void* d_out, int out_size) {
    const int*   idx    = (const int*)  d_in[0];
    const float* tok    = (const float*)d_in[1];
    const float* q_emb  = (const float*)d_in[2];
    const float* a_emb  = (const float*)d_in[3];
    const float* pos    = (const float*)d_in[4];
    const float* ln1_s  = (const float*)d_in[5];
    const float* ln1_b  = (const float*)d_in[6];
    const float* attn_w = (const float*)d_in[7];
    const float* proj_w = (const float*)d_in[8];
    const float* ln2_s  = (const float*)d_in[9];
    const float* ln2_b  = (const float*)d_in[10];
    const float* mlp_w1 = (const float*)d_in[11];
    const float* mlp_b1 = (const float*)d_in[12];
    const float* mlp_w2 = (const float*)d_in[13];
    const float* mlp_b2 = (const float*)d_in[14];
    const float* lnf_s  = (const float*)d_in[15];
    const float* lnf_b  = (const float*)d_in[16];
    float* out = (float*)d_out;

    float *x, *qkv;
    __half *w16, *tok16, *a16, *m16, *q16, *v16;
    cudaGetSymbolAddress((void**)&x, g_x);
    cudaGetSymbolAddress((void**)&qkv, g_qkv);
    cudaGetSymbolAddress((void**)&w16, g_w16);
    cudaGetSymbolAddress((void**)&tok16, g_tok16);
    cudaGetSymbolAddress((void**)&a16, g_a16);
    cudaGetSymbolAddress((void**)&m16, g_m16);
    cudaGetSymbolAddress((void**)&q16, g_q16);
    cudaGetSymbolAddress((void**)&v16, g_v16);

    const int SG = 3 * STG16;                    // 98304
    const int SF = 18432 + 2 * 35840;            // 90112
    cudaFuncSetAttribute(tg16<0>, cudaFuncAttributeMaxDynamicSharedMemorySize, SG);
    cudaFuncSetAttribute(tg16<1>, cudaFuncAttributeMaxDynamicSharedMemorySize, SG);
    cudaFuncSetAttribute(tg16<2>, cudaFuncAttributeMaxDynamicSharedMemorySize, SG);
    cudaFuncSetAttribute(tg16<3>, cudaFuncAttributeMaxDynamicSharedMemorySize, SG);
    cudaFuncSetAttribute(tg16<5>, cudaFuncAttributeMaxDynamicSharedMemorySize, SG);
    cudaFuncSetAttribute(flash16, cudaFuncAttributeMaxDynamicSharedMemorySize, SF);

    const int M = BI * TT;
    const long C2 = (long)CC * CC;

    // order: wconv16(0), embed(1), ln16(2), tg16<5>(3) <- ncu profiles index 3
    wconv16<<<dim3(96, 32), 256>>>(attn_w, w16, CC, 3 * CC);
    embed_kernel<<<M, 256>>>(idx, tok, q_emb, a_emb, pos);

    for (int l = 0; l < LL; l++) {
        long wb = (long)l * 8 * C2;
        ln16_kernel<<<M, 256>>>(x, a16, ln1_s + (size_t)l * CC, ln1_b + (size_t)l * CC);
        tg16<5><<<dim3(32, 24), 256, SG>>>(M, 3 * CC, CC,
            a16, CC, w16 + wb, CC, nullptr, qkv, 3 * CC, q16);
        vconv16<<<dim3(32, 2, BI * HH), 256>>>(qkv);
        flash16<<<dim3(8, BI * HH), 256, SF>>>(q16, v16, a16);
        wconv16<<<dim3(32, 32), 256>>>(proj_w + (size_t)l * C2, w16 + wb + 3 * C2, CC, CC);
        tg16<1><<<dim3(32, 8), 256, SG>>>(M, CC, CC,
            a16, CC, w16 + wb + 3 * C2, CC, nullptr, x, CC, nullptr);
        ln16_kernel<<<M, 256>>>(x, a16, ln2_s + (size_t)l * CC, ln2_b + (size_t)l * CC);
        wconv16<<<dim3(64, 32), 256>>>(mlp_w1 + (size_t)l * 2 * C2, w16 + wb + 4 * C2, CC, 2 * CC);
        tg16<2><<<dim3(32, 16), 256, SG>>>(M, 2 * CC, CC,
            a16, CC, w16 + wb + 4 * C2, CC,
            mlp_b1 + (size_t)l * 2 * CC, nullptr, 2 * CC, m16);
        wconv16<<<dim3(32, 64), 256>>>(mlp_w2 + (size_t)l * 2 * C2, w16 + wb + 6 * C2, 2 * CC, CC);
        tg16<3><<<dim3(32, 8), 256, SG>>>(M, CC, 2 * CC,
            m16, 2 * CC, w16 + wb + 6 * C2, 2 * CC,
            mlp_b2 + (size_t)l * CC, x, CC, nullptr);
        if (l + 1 < LL)
            wconv16<<<dim3(96, 32), 256>>>(attn_w + (size_t)(l + 1) * 3 * C2, w16 + (long)(l + 1) * 8 * C2, CC, 3 * CC);
    }
    // head
    ln16_kernel<<<M, 256>>>(x, a16, lnf_s, lnf_b);
    aconv16<<<(int)(((long)VV * CC) / 1024), 256>>>(tok, tok16, (long)VV * CC);
    tg16<0><<<dim3(32, 250), 256, SG>>>(M, VV, CC, a16, CC, tok16, CC, nullptr, out, VV, nullptr);
}